// round 5
// baseline (speedup 1.0000x reference)
#include <cuda_runtime.h>
#include <stdint.h>
#include <math.h>

// Problem constants
#define N_SEQ   2048
#define S_SITES 4096
#define WPS     128          // 32-token bit-plane words per sequence (4096/32)
#define TILES   136          // 16*17/2 triangle tiles of 128x128
#define SMEM_STRIDE 18       // 16 words per chunk + 2 pad (bank-conflict-free LDS.64)

// Scratch (static device globals: allocation-free rule)
__device__ uint32_t g_lo[N_SEQ][WPS];     // low token bit plane
__device__ uint32_t g_hi[N_SEQ][WPS];     // high token bit plane
__device__ float4   g_zs[N_SEQ];          // {z.x, z.y, ||z||^2, 1/(1-||z||^2)}
__device__ float    g_scale;              // exp(log_scale)
__device__ float    g_partial[TILES];     // per-tile weighted partial sums

// ---------------------------------------------------------------------------
// Kernel 1: pack one-hot fp32 -> 2-bit token planes.
// data layout [N][S][A], A=4 contiguous. token t: onehot (x,y,z,w).
// low bit set for tokens {1,3} (y or w), high bit for {2,3} (z or w).
// ---------------------------------------------------------------------------
__global__ void pack_kernel(const float* __restrict__ data) {
    int gid = blockIdx.x * blockDim.x + threadIdx.x;   // 0 .. N_SEQ*WPS-1
    int n = gid >> 7;          // sequence
    int g = gid & 127;         // 32-site group
    const float4* p = reinterpret_cast<const float4*>(
        data + (size_t)n * (S_SITES * 4) + (size_t)g * 128);
    uint32_t lo = 0u, hi = 0u;
#pragma unroll
    for (int b = 0; b < 32; b++) {
        float4 v = p[b];
        uint32_t l = (v.y != 0.0f) | (v.w != 0.0f);
        uint32_t h = (v.z != 0.0f) | (v.w != 0.0f);
        lo |= l << b;
        hi |= h << b;
    }
    g_lo[n][g] = lo;
    g_hi[n][g] = hi;
}

// ---------------------------------------------------------------------------
// Kernel 2: normalize embedding table (tanh-clamp into unit ball), precompute
// squared norms and 1/(1-s), and the global exp(log_scale).
// ---------------------------------------------------------------------------
__global__ void prep_kernel(const float* __restrict__ table,
                            const float* __restrict__ log_scale) {
    int i = blockIdx.x * blockDim.x + threadIdx.x;
    if (i < N_SEQ) {
        float x = table[2 * i], y = table[2 * i + 1];
        float norm = sqrtf(x * x + y * y);
        float nm = fmaxf(norm, 1e-12f);
        float f = tanhf(norm) / nm;
        float zx = x * f, zy = y * f;
        float s = zx * zx + zy * zy;
        g_zs[i] = make_float4(zx, zy, s, 1.0f / (1.0f - s));
    }
    if (i == 0) g_scale = expf(log_scale[0]);
}

// ---------------------------------------------------------------------------
// Kernel 3: main. One CTA per 128x128 triangle tile (bj <= bi). Each thread
// owns an 8x8 pair subtile. Hamming counts via XOR/OR/POPC over the bit
// planes, then fused epilogue: hamming frac, hyperbolic distance, squared
// diff, tile-level reduction -> g_partial (weight 2 for off-diagonal tiles).
// ---------------------------------------------------------------------------
__global__ void __launch_bounds__(256) ham_kernel() {
    __shared__ uint32_t As_lo[128 * SMEM_STRIDE];
    __shared__ uint32_t As_hi[128 * SMEM_STRIDE];
    __shared__ uint32_t Bs_lo[128 * SMEM_STRIDE];
    __shared__ uint32_t Bs_hi[128 * SMEM_STRIDE];
    __shared__ float    wsum[8];

    int k = blockIdx.x;
    int bi = 0;
    while ((bi + 1) * (bi + 2) / 2 <= k) bi++;
    int bj = k - bi * (bi + 1) / 2;

    int tid = threadIdx.x;
    int tx = tid & 15;          // j-group selector
    int ty = tid >> 4;          // i-group selector

    int acc[8][8];
#pragma unroll
    for (int p = 0; p < 8; p++)
#pragma unroll
        for (int q = 0; q < 8; q++) acc[p][q] = 0;

    // 8 chunks of 16 plane-words (= 512 tokens) each
    for (int c = 0; c < 8; c++) {
        __syncthreads();
        // cooperative load: 4 planes x 128 rows x 8 uint2 = 4096 uint2
#pragma unroll
        for (int it = 0; it < 4; it++) {
            int idx = tid + 256 * it;      // 0..1023
            int row = idx >> 3;
            int u   = idx & 7;
            uint2 v;
            v = reinterpret_cast<const uint2*>(&g_lo[bi * 128 + row][c * 16])[u];
            *reinterpret_cast<uint2*>(&As_lo[row * SMEM_STRIDE + 2 * u]) = v;
            v = reinterpret_cast<const uint2*>(&g_hi[bi * 128 + row][c * 16])[u];
            *reinterpret_cast<uint2*>(&As_hi[row * SMEM_STRIDE + 2 * u]) = v;
            v = reinterpret_cast<const uint2*>(&g_lo[bj * 128 + row][c * 16])[u];
            *reinterpret_cast<uint2*>(&Bs_lo[row * SMEM_STRIDE + 2 * u]) = v;
            v = reinterpret_cast<const uint2*>(&g_hi[bj * 128 + row][c * 16])[u];
            *reinterpret_cast<uint2*>(&Bs_hi[row * SMEM_STRIDE + 2 * u]) = v;
        }
        __syncthreads();

        for (int k2 = 0; k2 < 8; k2++) {
            uint2 al[8], ah[8], bl[8], bh[8];
#pragma unroll
            for (int p = 0; p < 8; p++) {
                int r = (ty * 8 + p) * SMEM_STRIDE + 2 * k2;
                al[p] = *reinterpret_cast<const uint2*>(&As_lo[r]);
                ah[p] = *reinterpret_cast<const uint2*>(&As_hi[r]);
            }
#pragma unroll
            for (int q = 0; q < 8; q++) {
                int r = (q * 16 + tx) * SMEM_STRIDE + 2 * k2;
                bl[q] = *reinterpret_cast<const uint2*>(&Bs_lo[r]);
                bh[q] = *reinterpret_cast<const uint2*>(&Bs_hi[r]);
            }
#pragma unroll
            for (int p = 0; p < 8; p++) {
#pragma unroll
                for (int q = 0; q < 8; q++) {
                    // mismatch mask: token differs iff low OR high bit differs
                    uint32_t n0 = (al[p].x ^ bl[q].x) | (ah[p].x ^ bh[q].x);
                    uint32_t n1 = (al[p].y ^ bl[q].y) | (ah[p].y ^ bh[q].y);
                    acc[p][q] += __popc(n0) + __popc(n1);
                }
            }
        }
    }

    // ---------------- fused epilogue ----------------
    float scale = g_scale;
    float4 zi[8], zj[8];
#pragma unroll
    for (int p = 0; p < 8; p++) zi[p] = g_zs[bi * 128 + ty * 8 + p];
#pragma unroll
    for (int q = 0; q < 8; q++) zj[q] = g_zs[bj * 128 + q * 16 + tx];

    const float inv_s = 1.0f / 4096.0f;
    float sum = 0.0f;
#pragma unroll
    for (int p = 0; p < 8; p++) {
#pragma unroll
        for (int q = 0; q < 8; q++) {
            float ham = (float)acc[p][q] * inv_s;              // exact
            float dx = zi[p].x - zj[q].x;
            float dy = zi[p].y - zj[q].y;
            float dsq = dx * dx + dy * dy;
            float arg = fmaf(2.0f * dsq, zi[p].w * zj[q].w, 1.0f);
            arg = fmaxf(arg, 1.0f + 1e-7f);
            float dist = acoshf(arg) * scale;
            float d = ham - dist;
            sum = fmaf(d, d, sum);
        }
    }

    // warp tree reduce
#pragma unroll
    for (int o = 16; o > 0; o >>= 1)
        sum += __shfl_down_sync(0xffffffffu, sum, o);
    if ((tid & 31) == 0) wsum[tid >> 5] = sum;
    __syncthreads();
    if (tid == 0) {
        float t = 0.0f;
#pragma unroll
        for (int w = 0; w < 8; w++) t += wsum[w];
        g_partial[k] = t * ((bi == bj) ? 1.0f : 2.0f);
    }
}

// ---------------------------------------------------------------------------
// Kernel 4: deterministic final reduce of 136 tile partials -> mean.
// ---------------------------------------------------------------------------
__global__ void final_kernel(float* __restrict__ out) {
    __shared__ float sh[256];
    int t = threadIdx.x;
    sh[t] = (t < TILES) ? g_partial[t] : 0.0f;
    __syncthreads();
    for (int o = 128; o > 0; o >>= 1) {
        if (t < o) sh[t] += sh[t + o];
        __syncthreads();
    }
    if (t == 0) out[0] = sh[0] * (1.0f / 4194304.0f);   // / 2048^2 (exact pow2)
}

// ---------------------------------------------------------------------------
extern "C" void kernel_launch(void* const* d_in, const int* in_sizes, int n_in,
                              void* d_out, int out_size) {
    const float* data   = (const float*)d_in[0];   // [2048,4096,4] fp32 one-hot
    const float* table  = (const float*)d_in[1];   // [2048,2] fp32
    const float* lscale = (const float*)d_in[2];   // scalar fp32

    (void)in_sizes; (void)n_in; (void)out_size;

    pack_kernel <<<(N_SEQ * WPS) / 256, 256>>>(data);
    prep_kernel <<<(N_SEQ + 255) / 256, 256>>>(table, lscale);
    ham_kernel  <<<TILES, 256>>>();
    final_kernel<<<1, 256>>>((float*)d_out);
}

// round 7
// speedup vs baseline: 1.3877x; 1.3877x over previous
#include <cuda_runtime.h>
#include <stdint.h>
#include <math.h>

// Problem constants
#define N_SEQ   2048
#define S_SITES 4096
#define WPS     128          // (lo,hi) uint2 words per sequence, 32 tokens each
#define TILES   136          // 16*17/2 triangle tiles of 128x128
#define STR     17           // smem row stride in uint2 (conflict-free)

// Scratch (static device globals: allocation-free rule)
__device__ uint2    g_ab[N_SEQ * WPS];   // interleaved bit planes (lo, hi)
__device__ float4   g_zs[N_SEQ];         // {z.x, z.y, ||z||^2, 1/(1-||z||^2)}
__device__ float    g_scale;             // exp(log_scale)
__device__ float    g_partial[TILES];    // per-tile weighted partial sums
__device__ unsigned g_count;             // zero-init; self-restoring ticket

// ---------------------------------------------------------------------------
// Kernel 1: pack one-hot fp32 -> bit planes (ballot-based, coalesced) and,
// in blocks 0..7, also normalize the embedding table (fused prep).
// One thread = one site (16B). Warp reads 512 contiguous bytes; the 32-bit
// plane word is assembled with __ballot_sync. one-hot 1.0f = 0x3F800000, so
// bit 29 of the OR of the relevant lanes is the token bit — no FSETP chain.
// ---------------------------------------------------------------------------
__global__ void pack_prep_kernel(const float* __restrict__ data,
                                 const float* __restrict__ table,
                                 const float* __restrict__ log_scale) {
    unsigned site = blockIdx.x * 256u + threadIdx.x;   // 0 .. N*S-1
    uint4 u = reinterpret_cast<const uint4*>(data)[site];
    unsigned lo = __ballot_sync(0xffffffffu, (int)((u.y | u.w) & 0x20000000u));
    unsigned hi = __ballot_sync(0xffffffffu, (int)((u.z | u.w) & 0x20000000u));
    if ((threadIdx.x & 31u) == 0u)
        g_ab[site >> 5] = make_uint2(lo, hi);

    // fused prep: 8 blocks x 256 threads = 2048 rows
    if (blockIdx.x < 8) {
        int i = blockIdx.x * 256 + threadIdx.x;
        float x = table[2 * i], y = table[2 * i + 1];
        float norm = sqrtf(x * x + y * y);
        float nm = fmaxf(norm, 1e-12f);
        float f = tanhf(norm) / nm;
        float zx = x * f, zy = y * f;
        float s = zx * zx + zy * zy;
        g_zs[i] = make_float4(zx, zy, s, 1.0f / (1.0f - s));
        if (i == 0) g_scale = expf(log_scale[0]);
    }
}

// ---------------------------------------------------------------------------
// Kernel 2: main. One CTA (512 threads) per 128x128 triangle tile (bj <= bi).
// Thread tile 8(i) x 4(j). Warp id = i-group -> a-loads are smem broadcasts;
// lane id strides b-rows (stride-17 rows, conflict-free LDS.64).
// Fused epilogue (hyperbolic distance + MSE) and last-CTA final reduction.
// ---------------------------------------------------------------------------
__global__ void __launch_bounds__(512) ham_kernel(float* __restrict__ out) {
    __shared__ uint2 As[128 * STR];
    __shared__ uint2 Bs[128 * STR];
    __shared__ float wsum[16];
    __shared__ int   s_last;

    int k = blockIdx.x;
    int bi = 0;
    while ((bi + 1) * (bi + 2) / 2 <= k) bi++;
    int bj = k - bi * (bi + 1) / 2;

    int tid = threadIdx.x;
    int tx = tid & 31;          // lane: j fine index
    int ty = tid >> 5;          // warp: i group (0..15)

    int acc[8][4];
#pragma unroll
    for (int p = 0; p < 8; p++)
#pragma unroll
        for (int q = 0; q < 4; q++) acc[p][q] = 0;

    const uint4* gA = reinterpret_cast<const uint4*>(g_ab + (size_t)bi * 128 * WPS);
    const uint4* gB = reinterpret_cast<const uint4*>(g_ab + (size_t)bj * 128 * WPS);

    // 8 chunks of 16 (lo,hi)-words (= 512 tokens) each
    for (int c = 0; c < 8; c++) {
        __syncthreads();
        // cooperative load: 1024 uint4 per matrix, 512 threads x 2
#pragma unroll
        for (int it = 0; it < 2; it++) {
            int idx4 = tid + it * 512;       // 0..1023
            int row  = idx4 >> 3;
            int c4   = idx4 & 7;
            uint4 va = gA[row * 64 + c * 8 + c4];
            uint4 vb = gB[row * 64 + c * 8 + c4];
            As[row * STR + 2 * c4    ] = make_uint2(va.x, va.y);
            As[row * STR + 2 * c4 + 1] = make_uint2(va.z, va.w);
            Bs[row * STR + 2 * c4    ] = make_uint2(vb.x, vb.y);
            Bs[row * STR + 2 * c4 + 1] = make_uint2(vb.z, vb.w);
        }
        __syncthreads();

#pragma unroll 4
        for (int kk = 0; kk < 16; kk++) {
            uint2 a[8], b[4];
#pragma unroll
            for (int p = 0; p < 8; p++)
                a[p] = As[(ty * 8 + p) * STR + kk];     // warp-broadcast
#pragma unroll
            for (int q = 0; q < 4; q++)
                b[q] = Bs[(q * 32 + tx) * STR + kk];
#pragma unroll
            for (int p = 0; p < 8; p++)
#pragma unroll
                for (int q = 0; q < 4; q++) {
                    // token differs iff low OR high plane bit differs
                    unsigned m = (a[p].x ^ b[q].x) | (a[p].y ^ b[q].y);
                    acc[p][q] += __popc(m);
                }
        }
    }

    // ---------------- fused epilogue ----------------
    float scale = g_scale;
    float4 zi[8], zj[4];
#pragma unroll
    for (int p = 0; p < 8; p++) zi[p] = g_zs[bi * 128 + ty * 8 + p];
#pragma unroll
    for (int q = 0; q < 4; q++) zj[q] = g_zs[bj * 128 + q * 32 + tx];

    const float inv_s = 1.0f / 4096.0f;
    float sum = 0.0f;
#pragma unroll
    for (int p = 0; p < 8; p++)
#pragma unroll
        for (int q = 0; q < 4; q++) {
            float ham = (float)acc[p][q] * inv_s;          // exact
            float dx = zi[p].x - zj[q].x;
            float dy = zi[p].y - zj[q].y;
            float dsq = dx * dx + dy * dy;
            float arg = fmaf(2.0f * dsq, zi[p].w * zj[q].w, 1.0f);
            arg = fmaxf(arg, 1.0f + 1e-7f);
            float dist = acoshf(arg) * scale;
            float d = ham - dist;
            sum = fmaf(d, d, sum);
        }

    // tile reduction
#pragma unroll
    for (int o = 16; o > 0; o >>= 1)
        sum += __shfl_down_sync(0xffffffffu, sum, o);
    if (tx == 0) wsum[ty] = sum;
    __syncthreads();
    if (tid == 0) {
        float t = 0.0f;
#pragma unroll
        for (int w = 0; w < 16; w++) t += wsum[w];
        g_partial[k] = t * ((bi == bj) ? 1.0f : 2.0f);
        __threadfence();
        unsigned tk = atomicAdd(&g_count, 1u);
        s_last = (tk == TILES - 1);
    }
    __syncthreads();

    // last CTA: deterministic final reduce (fixed order every replay)
    if (s_last) {
        float v = (tid < TILES) ? g_partial[tid] : 0.0f;
#pragma unroll
        for (int o = 16; o > 0; o >>= 1)
            v += __shfl_down_sync(0xffffffffu, v, o);
        __syncthreads();                 // wsum reuse
        if (tx == 0) wsum[ty] = v;
        __syncthreads();
        if (tid == 0) {
            float t = 0.0f;
#pragma unroll
            for (int w = 0; w < 16; w++) t += wsum[w];
            out[0] = t * (1.0f / 4194304.0f);   // / 2048^2
            g_count = 0u;                        // self-restore for graph replay
        }
    }
}

// ---------------------------------------------------------------------------
extern "C" void kernel_launch(void* const* d_in, const int* in_sizes, int n_in,
                              void* d_out, int out_size) {
    const float* data   = (const float*)d_in[0];   // [2048,4096,4] fp32 one-hot
    const float* table  = (const float*)d_in[1];   // [2048,2] fp32
    const float* lscale = (const float*)d_in[2];   // scalar fp32

    (void)in_sizes; (void)n_in; (void)out_size;

    pack_prep_kernel<<<(N_SEQ * S_SITES) / 256, 256>>>(data, table, lscale);
    ham_kernel      <<<TILES, 512>>>((float*)d_out);
}

// round 8
// speedup vs baseline: 1.4143x; 1.0192x over previous
#include <cuda_runtime.h>
#include <stdint.h>
#include <math.h>

// Problem constants
#define N_SEQ   2048
#define S_SITES 4096
#define WPS     128          // (lo,hi) uint2 words per sequence, 32 tokens each
#define WPS4    64           // uint4 view: 64 per sequence (each = 2 kk words)
#define TILES   136          // 16*17/2 triangle tiles of 128x128
#define STR4    5            // smem row stride in uint4 (4 data + 1 pad)
#define NCHUNK  16           // 16 chunks x 4 uint4/row each

// Scratch (static device globals: allocation-free rule)
__device__ uint2    g_ab[N_SEQ * WPS];   // interleaved bit planes (lo, hi)
__device__ float4   g_zs[N_SEQ];         // {z.x, z.y, ||z||^2, 1/(1-||z||^2)}
__device__ float    g_scale;             // exp(log_scale)
__device__ float    g_partial[TILES];    // per-tile weighted partial sums
__device__ unsigned g_count;             // zero-init; self-restoring ticket

// ---------------------------------------------------------------------------
// Kernel 1: pack one-hot fp32 -> bit planes (ballot-based, coalesced) and,
// in blocks 0..7, also normalize the embedding table (fused prep).
// One thread = one site (16B). one-hot 1.0f = 0x3F800000, so bit 29 of the
// OR of the relevant lanes IS the token bit — no float compares needed.
// ---------------------------------------------------------------------------
__global__ void pack_prep_kernel(const float* __restrict__ data,
                                 const float* __restrict__ table,
                                 const float* __restrict__ log_scale) {
    unsigned site = blockIdx.x * 256u + threadIdx.x;   // 0 .. N*S-1
    uint4 u = reinterpret_cast<const uint4*>(data)[site];
    unsigned lo = __ballot_sync(0xffffffffu, (int)((u.y | u.w) & 0x20000000u));
    unsigned hi = __ballot_sync(0xffffffffu, (int)((u.z | u.w) & 0x20000000u));
    if ((threadIdx.x & 31u) == 0u)
        g_ab[site >> 5] = make_uint2(lo, hi);

    // fused prep: 8 blocks x 256 threads = 2048 rows
    if (blockIdx.x < 8) {
        int i = blockIdx.x * 256 + threadIdx.x;
        float x = table[2 * i], y = table[2 * i + 1];
        float norm = sqrtf(x * x + y * y);
        float nm = fmaxf(norm, 1e-12f);
        float f = tanhf(norm) / nm;
        float zx = x * f, zy = y * f;
        float s = zx * zx + zy * zy;
        g_zs[i] = make_float4(zx, zy, s, 1.0f / (1.0f - s));
        if (i == 0) g_scale = expf(log_scale[0]);
    }
}

// ---------------------------------------------------------------------------
// Kernel 2: main. One CTA (512 threads) per 128x128 triangle tile (bj <= bi).
// Thread tile 8(i) x 4(j). Double-buffered smem (uint4 rows, stride 5),
// register-prefetched global loads, one __syncthreads per chunk.
// Each uint4 = two (lo,hi) plane words = 64 tokens; popcs pair-accumulated
// into IADD3. Fused hyperbolic-distance epilogue + last-CTA reduction.
// ---------------------------------------------------------------------------
__global__ void __launch_bounds__(512) ham_kernel(float* __restrict__ out) {
    __shared__ uint4 As4[2][128 * STR4];
    __shared__ uint4 Bs4[2][128 * STR4];
    __shared__ float wsum[16];
    __shared__ int   s_last;

    int k = blockIdx.x;
    int bi = 0;
    while ((bi + 1) * (bi + 2) / 2 <= k) bi++;
    int bj = k - bi * (bi + 1) / 2;

    int tid = threadIdx.x;
    int tx = tid & 31;          // lane: j fine index
    int ty = tid >> 5;          // warp: i group (0..15)

    // cooperative-load assignment: 512 threads = 128 rows x 4 uint4
    int lrow = tid >> 2;
    int lc4  = tid & 3;

    int acc[8][4];
#pragma unroll
    for (int p = 0; p < 8; p++)
#pragma unroll
        for (int q = 0; q < 4; q++) acc[p][q] = 0;

    const uint4* gA = reinterpret_cast<const uint4*>(g_ab) + (size_t)(bi * 128 + lrow) * WPS4 + lc4;
    const uint4* gB = reinterpret_cast<const uint4*>(g_ab) + (size_t)(bj * 128 + lrow) * WPS4 + lc4;

    // prologue: chunk 0 into buffer 0
    uint4 va = gA[0];
    uint4 vb = gB[0];
    As4[0][lrow * STR4 + lc4] = va;
    Bs4[0][lrow * STR4 + lc4] = vb;
    __syncthreads();

    for (int c = 0; c < NCHUNK; c++) {
        int cur = c & 1;
        // prefetch next chunk to registers (overlaps with compute below)
        if (c < NCHUNK - 1) {
            va = gA[(c + 1) * 4];
            vb = gB[(c + 1) * 4];
        }

        const uint4* A = As4[cur];
        const uint4* B = Bs4[cur];
#pragma unroll
        for (int kp = 0; kp < 4; kp++) {
            uint4 a[8], b[4];
#pragma unroll
            for (int p = 0; p < 8; p++)
                a[p] = A[(ty * 8 + p) * STR4 + kp];     // warp-broadcast
#pragma unroll
            for (int q = 0; q < 4; q++)
                b[q] = B[(q * 32 + tx) * STR4 + kp];
#pragma unroll
            for (int p = 0; p < 8; p++)
#pragma unroll
                for (int q = 0; q < 4; q++) {
                    // token differs iff low OR high plane bit differs
                    unsigned m0 = (a[p].x ^ b[q].x) | (a[p].y ^ b[q].y);
                    unsigned m1 = (a[p].z ^ b[q].z) | (a[p].w ^ b[q].w);
                    acc[p][q] += __popc(m0) + __popc(m1);   // IADD3
                }
        }

        if (c < NCHUNK - 1) {
            int nxt = cur ^ 1;
            As4[nxt][lrow * STR4 + lc4] = va;
            Bs4[nxt][lrow * STR4 + lc4] = vb;
            __syncthreads();
        }
    }

    // ---------------- fused epilogue ----------------
    float scale = g_scale;
    float4 zi[8], zj[4];
#pragma unroll
    for (int p = 0; p < 8; p++) zi[p] = g_zs[bi * 128 + ty * 8 + p];
#pragma unroll
    for (int q = 0; q < 4; q++) zj[q] = g_zs[bj * 128 + q * 32 + tx];

    const float inv_s = 1.0f / 4096.0f;
    float sum = 0.0f;
#pragma unroll
    for (int p = 0; p < 8; p++)
#pragma unroll
        for (int q = 0; q < 4; q++) {
            float ham = (float)acc[p][q] * inv_s;          // exact
            float dx = zi[p].x - zj[q].x;
            float dy = zi[p].y - zj[q].y;
            float dsq = dx * dx + dy * dy;
            float arg = fmaf(2.0f * dsq, zi[p].w * zj[q].w, 1.0f);
            arg = fmaxf(arg, 1.0f + 1e-7f);
            float dist = acoshf(arg) * scale;
            float d = ham - dist;
            sum = fmaf(d, d, sum);
        }

    // tile reduction
#pragma unroll
    for (int o = 16; o > 0; o >>= 1)
        sum += __shfl_down_sync(0xffffffffu, sum, o);
    if (tx == 0) wsum[ty] = sum;
    __syncthreads();
    if (tid == 0) {
        float t = 0.0f;
#pragma unroll
        for (int w = 0; w < 16; w++) t += wsum[w];
        g_partial[k] = t * ((bi == bj) ? 1.0f : 2.0f);
        __threadfence();
        unsigned tk = atomicAdd(&g_count, 1u);
        s_last = (tk == TILES - 1);
    }
    __syncthreads();

    // last CTA: deterministic final reduce (fixed order every replay)
    if (s_last) {
        float v = (tid < TILES) ? g_partial[tid] : 0.0f;
#pragma unroll
        for (int o = 16; o > 0; o >>= 1)
            v += __shfl_down_sync(0xffffffffu, v, o);
        __syncthreads();                 // wsum reuse
        if (tx == 0) wsum[ty] = v;
        __syncthreads();
        if (tid == 0) {
            float t = 0.0f;
#pragma unroll
            for (int w = 0; w < 16; w++) t += wsum[w];
            out[0] = t * (1.0f / 4194304.0f);   // / 2048^2
            g_count = 0u;                        // self-restore for graph replay
        }
    }
}

// ---------------------------------------------------------------------------
extern "C" void kernel_launch(void* const* d_in, const int* in_sizes, int n_in,
                              void* d_out, int out_size) {
    const float* data   = (const float*)d_in[0];   // [2048,4096,4] fp32 one-hot
    const float* table  = (const float*)d_in[1];   // [2048,2] fp32
    const float* lscale = (const float*)d_in[2];   // scalar fp32

    (void)in_sizes; (void)n_in; (void)out_size;

    pack_prep_kernel<<<(N_SEQ * S_SITES) / 256, 256>>>(data, table, lscale);
    ham_kernel      <<<TILES, 512>>>((float*)d_out);
}